// round 15
// baseline (speedup 1.0000x reference)
#include <cuda_runtime.h>

// SNN: T=512, B=64, I=1024, H=4096, O=1024, alpha=beta=0.9, thresh=1.0
// Bit-exact reference arithmetic (proven R13/R14):
//   GEMM2: splitK=2  (512-chunks), ascending fp32 FMA chain, combine ascending
//   GEMM3: splitK=8  (512-chunks), same
// R15: 512 thr/CTA (4 warps/SMSP), k-contiguous undup spike staging
//      (1.5 LDS.128 per k), register f32x2 duplication, KBLK=32.
#define Tn 512
#define Bn 64
#define In 1024
#define Hn 4096
#define On 1024

#define NCTA 128
#define NTHR 512
#define NTOT (NCTA * NTHR)

#define KBLK 32
#define SPAD 36

// ---------------- persistent device state ----------------
__device__ float g_s1[Bn * In], g_m1[Bn * In], g_spk1[Bn * In];
__device__ float g_s2[Bn * Hn], g_m2[Bn * Hn], g_spk2[Bn * Hn];
__device__ float g_s3[Bn * On], g_m3[Bn * On];
__device__ float g_w1t[In * Hn];   // w1 transposed: [k][h]
__device__ float g_w2t[Hn * On];   // w2 transposed: [k][o]
__device__ float g_p2[2][Bn * Hn]; // GEMM2 chunk partials
__device__ float g_p3[8][Bn * On]; // GEMM3 chunk partials
__device__ unsigned g_cnt, g_gen;

// ---------------- grid-wide barrier (proven) ----------------
__device__ __forceinline__ void gridbar() {
    __syncthreads();
    if (threadIdx.x == 0) {
        __threadfence();
        unsigned gen = *(volatile unsigned*)&g_gen;
        if (atomicAdd(&g_cnt, 1u) == (unsigned)(NCTA - 1)) {
            g_cnt = 0;
            __threadfence();
            atomicAdd(&g_gen, 1u);
        } else {
            while (*(volatile unsigned*)&g_gen == gen) { __nanosleep(64); }
        }
        __threadfence();
    }
    __syncthreads();
}

// packed f32x2 FMA: two independent fp32 FMAs, bit-identical to scalar FFMA
#define FMA2(d, a, b) asm("fma.rn.f32x2 %0, %1, %2, %0;" : "+l"(d) : "l"(a), "l"(b))

// duplicate a float into both lanes of a 64-bit f32x2 operand (alu mov)
__device__ __forceinline__ unsigned long long dup2(float s) {
    unsigned long long d;
    asm("mov.b64 %0, {%1, %1};" : "=l"(d) : "f"(s));
    return d;
}

__device__ __forceinline__ float neuron_step(float* __restrict__ S,
                                             float* __restrict__ M,
                                             size_t idx, float inp) {
    float s = S[idx], m = M[idx];
    float r = (m > 1.0f) ? 1.0f : 0.0f;
    s = __fmaf_rn(0.9f, s, inp);
    m = __fsub_rn(__fmaf_rn(0.9f, m, s), r);
    S[idx] = s; M[idx] = m;
    return (m > 1.0f) ? 1.0f : 0.0f;
}

// ---------------- one 512-k chunk of a GEMM, one CTA ----------------
// part[b][n] (64 b x 64 n at n0) = fold_{k=k0}^{k0+512} spk[b][k]*wT[k][n],
// single fp32 accumulator per element, strictly ascending k (bit-exact).
// 512 threads; thread owns 2 b x 4 n (4 f32x2 chains).
template<int KDIM, int NDIM>
__device__ __forceinline__ void gemm_chunk(const float* __restrict__ wT,
                                           const float* __restrict__ spk,
                                           float* __restrict__ part,
                                           int n0, int k0,
                                           float* __restrict__ w_s,
                                           float* __restrict__ s_s) {
    const int tid = threadIdx.x;
    const int hg  = tid & 15;          // n-group: 4 n at n0 + hg*4
    const int b0  = (tid >> 4) * 2;    // first of 2 b
    const int wr  = tid >> 4, wc = tid & 15;   // w staging: k-row(32), float4-col(16)
    const int sb  = tid >> 3, sk = tid & 7;    // s staging: b(64), k-quad(8)

    unsigned long long acc[2][2] = {{0ull, 0ull}, {0ull, 0ull}};

    float4 wv, sv;
    // prologue: fetch + stage block 0
    wv = *(const float4*)(wT + (size_t)(k0 + wr) * NDIM + n0 + wc * 4);
    sv = __ldcv((const float4*)(spk + (size_t)sb * KDIM + k0 + sk * 4));
    *(float4*)(w_s + wr * 64 + wc * 4) = wv;
    *(float4*)(s_s + sb * SPAD + sk * 4) = sv;
    __syncthreads();

    int buf = 0;
#pragma unroll 1
    for (int blk = 0; blk < 512 / KBLK; blk++) {
        const bool more = (blk + 1 < 512 / KBLK);
        if (more) {  // prefetch next block into registers
            const int kb = k0 + (blk + 1) * KBLK;
            wv = *(const float4*)(wT + (size_t)(kb + wr) * NDIM + n0 + wc * 4);
            sv = __ldcv((const float4*)(spk + (size_t)sb * KDIM + kb + sk * 4));
        }
        const float* wb = w_s + buf * (KBLK * 64);
        const float* sd = s_s + buf * (Bn * SPAD);
#pragma unroll
        for (int q = 0; q < KBLK / 4; q++) {          // 4-k quads
            float4 sp0 = *(const float4*)(sd + b0 * SPAD + q * 4);
            float4 sp1 = *(const float4*)(sd + (b0 + 1) * SPAD + q * 4);
#pragma unroll
            for (int j = 0; j < 4; j++) {
                ulonglong2 w2 = *(const ulonglong2*)(wb + (q * 4 + j) * 64 + hg * 4);
                unsigned long long a0 = dup2(((const float*)&sp0)[j]);
                unsigned long long a1 = dup2(((const float*)&sp1)[j]);
                FMA2(acc[0][0], a0, w2.x); FMA2(acc[0][1], a0, w2.y);
                FMA2(acc[1][0], a1, w2.x); FMA2(acc[1][1], a1, w2.y);
            }
        }
        if (more) {  // stage prefetched block into alternate buffer
            const int nb = buf ^ 1;
            *(float4*)(w_s + nb * (KBLK * 64) + wr * 64 + wc * 4) = wv;
            *(float4*)(s_s + nb * (Bn * SPAD) + sb * SPAD + sk * 4) = sv;
        }
        __syncthreads();
        buf ^= 1;
    }
    // write chunk partials
#pragma unroll
    for (int i = 0; i < 2; i++) {
        float2 a = *(float2*)&acc[i][0];
        float2 b = *(float2*)&acc[i][1];
        float4 o; o.x = a.x; o.y = a.y; o.z = b.x; o.w = b.y;
        *(float4*)(part + (size_t)(b0 + i) * NDIM + n0 + hg * 4) = o;
    }
}

// ---------------- elementwise phases ----------------
__device__ __forceinline__ void phaseA(const float* __restrict__ x, int t, int gt) {
    const float* xt = x + (size_t)t * Bn * In;
    for (int i = gt; i < Bn * In; i += NTOT)
        g_spk1[i] = neuron_step(g_s1, g_m1, i, xt[i]);
}

__device__ __forceinline__ void phaseL2(int gt) {
    for (int i = gt; i < Bn * Hn; i += NTOT) {
        float cur = __fadd_rn(__ldcv(&g_p2[0][i]), __ldcv(&g_p2[1][i]));
        g_spk2[i] = neuron_step(g_s2, g_m2, i, cur);
    }
}

__device__ __forceinline__ void phaseL3(float* __restrict__ out, int t, int gt) {
    float* ot = out + (size_t)t * Bn * On;
    for (int i = gt; i < Bn * On; i += NTOT) {
        float cur = __ldcv(&g_p3[0][i]);
#pragma unroll
        for (int c = 1; c < 8; c++) cur = __fadd_rn(cur, __ldcv(&g_p3[c][i]));
        ot[i] = neuron_step(g_s3, g_m3, i, cur);
    }
}

// ---------------- persistent kernel ----------------
__global__ void __launch_bounds__(NTHR, 1)
snn_kernel(const float* __restrict__ x, const float* __restrict__ w1,
           const float* __restrict__ w2, float* __restrict__ out) {
    __shared__ float w_s[2 * KBLK * 64];    // [buf][32 k][64 n]
    __shared__ float s_s[2 * Bn * SPAD];    // [buf][64 b][32 k + pad]
    const int gt = blockIdx.x * NTHR + threadIdx.x;

    // init: zero neuron state; transpose weights (exact fp32 copies)
    for (int i = gt; i < Bn * In; i += NTOT) { g_s1[i] = 0.0f; g_m1[i] = 0.0f; }
    for (int i = gt; i < Bn * Hn; i += NTOT) { g_s2[i] = 0.0f; g_m2[i] = 0.0f; }
    for (int i = gt; i < Bn * On; i += NTOT) { g_s3[i] = 0.0f; g_m3[i] = 0.0f; }
    for (int e = gt; e < In * Hn; e += NTOT) {
        int k = e >> 12, h = e & (Hn - 1);
        g_w1t[e] = w1[(size_t)h * In + k];
    }
    for (int e = gt; e < Hn * On; e += NTOT) {
        int k = e >> 10, o = e & (On - 1);
        g_w2t[e] = w2[(size_t)o * Hn + k];
    }
    gridbar();

    phaseA(x, 0, gt);
    gridbar();

    for (int t = 0; t < Tn; t++) {
        // P1: GEMM2 chunk partials. item = (chunk: bid>>6, h-tile: bid&63)
        {
            const int chunk = blockIdx.x >> 6;
            const int h0 = (blockIdx.x & 63) * 64;
            gemm_chunk<In, Hn>(g_w1t, g_spk1, g_p2[chunk], h0, chunk * 512, w_s, s_s);
        }
        gridbar();
        // P2: layer-2 neurons (combine p2); layer-3 (t-1); layer-1 (t+1)
        phaseL2(gt);
        if (t > 0) phaseL3(out, t - 1, gt);
        if (t + 1 < Tn) phaseA(x, t + 1, gt);
        gridbar();
        // P3: GEMM3 chunk partials. item = (chunk: bid>>4, o-tile: bid&15)
        {
            const int chunk = blockIdx.x >> 4;
            const int o0 = (blockIdx.x & 15) * 64;
            gemm_chunk<Hn, On>(g_w2t, g_spk2, g_p3[chunk], o0, chunk * 512, w_s, s_s);
        }
        gridbar();
    }
    phaseL3(out, Tn - 1, gt);
}

extern "C" void kernel_launch(void* const* d_in, const int* in_sizes, int n_in,
                              void* d_out, int out_size) {
    const float* x  = (const float*)d_in[0];   // [512,64,1024]
    const float* w1 = (const float*)d_in[1];   // [4096,1024]
    const float* w2 = (const float*)d_in[2];   // [1024,4096]
    float* out = (float*)d_out;                // [512,64,1024]
    snn_kernel<<<NCTA, NTHR>>>(x, w1, w2, out);
}

// round 16
// speedup vs baseline: 1.2616x; 1.2616x over previous
#include <cuda_runtime.h>

// SNN: T=512, B=64, I=1024, H=4096, O=1024, alpha=beta=0.9, thresh=1.0
// Bit-exact reference arithmetic (proven R13-R15):
//   GEMM2: splitK=2 (512-chunks), ascending fp32 FMA chain, combine ascending
//   GEMM3: splitK=8 (512-chunks), same
// R16: [n][b]-major global layouts everywhere (no transposes/dup in GEMM),
//      warp footprint 32n x 16b -> 2 smem wavefronts per 8 FMA2 (fma-bound).
#define Tn 512
#define Bn 64
#define In 1024
#define Hn 4096
#define On 1024

#define NCTA 128
#define NTHR 256
#define NTOT (NCTA * NTHR)

#define KBLK 32

typedef unsigned long long ull;

// ---------------- persistent device state ----------------
__device__ float g_xt[Tn * In * Bn];          // x transposed: [t][i][b]
__device__ float g_s1[In * Bn], g_m1[In * Bn], g_spk1[In * Bn];   // [i][b]
__device__ float g_s2[Hn * Bn], g_m2[Hn * Bn], g_spk2[Hn * Bn];   // [h][b]
__device__ float g_s3[On * Bn], g_m3[On * Bn];                    // [o][b]
__device__ float g_w1t[In * Hn];              // w1 transposed: [k][h]
__device__ float g_w2t[Hn * On];              // w2 transposed: [k][o]
__device__ float g_p2[2][Hn * Bn];            // GEMM2 chunk partials [n][b]
__device__ float g_p3[8][On * Bn];            // GEMM3 chunk partials [n][b]
__device__ unsigned g_cnt, g_gen;

// ---------------- grid-wide barrier (proven) ----------------
__device__ __forceinline__ void gridbar() {
    __syncthreads();
    if (threadIdx.x == 0) {
        __threadfence();
        unsigned gen = *(volatile unsigned*)&g_gen;
        if (atomicAdd(&g_cnt, 1u) == (unsigned)(NCTA - 1)) {
            g_cnt = 0;
            __threadfence();
            atomicAdd(&g_gen, 1u);
        } else {
            while (*(volatile unsigned*)&g_gen == gen) { __nanosleep(64); }
        }
        __threadfence();
    }
    __syncthreads();
}

// packed f32x2 FMA: two independent fp32 FMAs, bit-identical to scalar FFMA
#define FMA2(d, a, b) asm("fma.rn.f32x2 %0, %1, %2, %0;" : "+l"(d) : "l"(a), "l"(b))

// duplicate a float into both lanes of an f32x2 operand
__device__ __forceinline__ ull dup2(float s) {
    ull d;
    asm("mov.b64 %0, {%1, %1};" : "=l"(d) : "f"(s));
    return d;
}

__device__ __forceinline__ float neuron_step(float* __restrict__ S,
                                             float* __restrict__ M,
                                             size_t idx, float inp) {
    float s = S[idx], m = M[idx];
    float r = (m > 1.0f) ? 1.0f : 0.0f;
    s = __fmaf_rn(0.9f, s, inp);
    m = __fsub_rn(__fmaf_rn(0.9f, m, s), r);
    S[idx] = s; M[idx] = m;
    return (m > 1.0f) ? 1.0f : 0.0f;
}

// ---------------- one 512-k chunk of a GEMM, one CTA ----------------
// part[n][b] (64 n at n0 x 64 b) = fold_{k=k0}^{k0+512} spkT[k][b]*wT[k][n],
// single fp32 accumulator per element, strictly ascending k (bit-exact).
// 256 threads; thread = 4b x 4n. Warp footprint 32n x 16b.
template<int NDIM>
__device__ __forceinline__ void gemm_chunk(const float* __restrict__ wT,
                                           const float* __restrict__ spkT,
                                           float* __restrict__ part,
                                           int n0, int k0,
                                           float* __restrict__ w_s,
                                           float* __restrict__ s_s) {
    const int tid  = threadIdx.x;
    const int lane = tid & 31, wid = tid >> 5;
    const int nl = (wid & 1) * 32 + (lane & 7) * 4;   // local n (0..63)
    const int bl = (wid >> 1) * 16 + (lane >> 3) * 4; // local b (0..63)
    const int sr = tid >> 4, sc = tid & 15;           // staging: row, float4-col

    ull acc[2][4];
#pragma unroll
    for (int i = 0; i < 2; i++)
#pragma unroll
        for (int j = 0; j < 4; j++) acc[i][j] = 0ull;

    float4 wv0, wv1, sv0, sv1;
    // prologue: fetch + stage block 0  (rows sr, sr+16 of [32k][64])
    wv0 = *(const float4*)(wT + (size_t)(k0 + sr) * NDIM + n0 + sc * 4);
    wv1 = *(const float4*)(wT + (size_t)(k0 + sr + 16) * NDIM + n0 + sc * 4);
    sv0 = __ldcv((const float4*)(spkT + (size_t)(k0 + sr) * Bn + sc * 4));
    sv1 = __ldcv((const float4*)(spkT + (size_t)(k0 + sr + 16) * Bn + sc * 4));
    *(float4*)(w_s + sr * 64 + sc * 4) = wv0;
    *(float4*)(w_s + (sr + 16) * 64 + sc * 4) = wv1;
    *(float4*)(s_s + sr * 64 + sc * 4) = sv0;
    *(float4*)(s_s + (sr + 16) * 64 + sc * 4) = sv1;
    __syncthreads();

    int buf = 0;
#pragma unroll 1
    for (int blk = 0; blk < 512 / KBLK; blk++) {
        const bool more = (blk + 1 < 512 / KBLK);
        if (more) {  // prefetch next block into registers
            const int kb = k0 + (blk + 1) * KBLK;
            wv0 = *(const float4*)(wT + (size_t)(kb + sr) * NDIM + n0 + sc * 4);
            wv1 = *(const float4*)(wT + (size_t)(kb + sr + 16) * NDIM + n0 + sc * 4);
            sv0 = __ldcv((const float4*)(spkT + (size_t)(kb + sr) * Bn + sc * 4));
            sv1 = __ldcv((const float4*)(spkT + (size_t)(kb + sr + 16) * Bn + sc * 4));
        }
        const float* wb = w_s + buf * (KBLK * 64);
        const float* sb = s_s + buf * (KBLK * 64);
#pragma unroll
        for (int kk = 0; kk < KBLK; kk++) {
            ulonglong2 sp = *(const ulonglong2*)(sb + kk * 64 + bl); // (b0,b1),(b2,b3)
            float4 wv = *(const float4*)(wb + kk * 64 + nl);
            ull w0 = dup2(wv.x), w1 = dup2(wv.y), w2 = dup2(wv.z), w3 = dup2(wv.w);
            FMA2(acc[0][0], sp.x, w0); FMA2(acc[0][1], sp.x, w1);
            FMA2(acc[0][2], sp.x, w2); FMA2(acc[0][3], sp.x, w3);
            FMA2(acc[1][0], sp.y, w0); FMA2(acc[1][1], sp.y, w1);
            FMA2(acc[1][2], sp.y, w2); FMA2(acc[1][3], sp.y, w3);
        }
        if (more) {  // stage prefetched block into alternate buffer
            const int nb = buf ^ 1;
            *(float4*)(w_s + nb * (KBLK * 64) + sr * 64 + sc * 4) = wv0;
            *(float4*)(w_s + nb * (KBLK * 64) + (sr + 16) * 64 + sc * 4) = wv1;
            *(float4*)(s_s + nb * (KBLK * 64) + sr * 64 + sc * 4) = sv0;
            *(float4*)(s_s + nb * (KBLK * 64) + (sr + 16) * 64 + sc * 4) = sv1;
        }
        __syncthreads();
        buf ^= 1;
    }
    // write chunk partials: part[n0+nl+j][bl..bl+3]
#pragma unroll
    for (int j = 0; j < 4; j++) {
        float2 a = *(float2*)&acc[0][j];
        float2 b = *(float2*)&acc[1][j];
        float4 o; o.x = a.x; o.y = a.y; o.z = b.x; o.w = b.y;
        *(float4*)(part + (size_t)(n0 + nl + j) * Bn + bl) = o;
    }
}

// ---------------- elementwise phases (all [n][b]-major, linear) ----------------
__device__ __forceinline__ void phaseA(int t, int gt) {
    const float* xt = g_xt + (size_t)t * In * Bn;
    for (int i = gt; i < In * Bn; i += NTOT)
        g_spk1[i] = neuron_step(g_s1, g_m1, i, xt[i]);
}

__device__ __forceinline__ void phaseL2(int gt) {
    for (int i = gt; i < Hn * Bn; i += NTOT) {
        float cur = __fadd_rn(__ldcv(&g_p2[0][i]), __ldcv(&g_p2[1][i]));
        g_spk2[i] = neuron_step(g_s2, g_m2, i, cur);
    }
}

__device__ __forceinline__ void phaseL3(float* __restrict__ out, int t, int gt) {
    float* ot = out + (size_t)t * Bn * On;
    for (int i = gt; i < On * Bn; i += NTOT) {
        float cur = __ldcv(&g_p3[0][i]);
#pragma unroll
        for (int c = 1; c < 8; c++) cur = __fadd_rn(cur, __ldcv(&g_p3[c][i]));
        float spk = neuron_step(g_s3, g_m3, i, cur);
        int o = i >> 6, b = i & 63;
        ot[(size_t)b * On + o] = spk;    // out stays [t][b][o]
    }
}

// ---------------- persistent kernel ----------------
__global__ void __launch_bounds__(NTHR, 1)
snn_kernel(const float* __restrict__ x, const float* __restrict__ w1,
           const float* __restrict__ w2, float* __restrict__ out) {
    __shared__ float w_s[2 * KBLK * 64];    // [buf][32 k][64 n]
    __shared__ float s_s[2 * KBLK * 64];    // [buf][32 k][64 b]
    const int gt = blockIdx.x * NTHR + threadIdx.x;

    // init: zero neuron state; transpose weights + x (exact fp32 copies)
    for (int i = gt; i < In * Bn; i += NTOT) { g_s1[i] = 0.0f; g_m1[i] = 0.0f; }
    for (int i = gt; i < Hn * Bn; i += NTOT) { g_s2[i] = 0.0f; g_m2[i] = 0.0f; }
    for (int i = gt; i < On * Bn; i += NTOT) { g_s3[i] = 0.0f; g_m3[i] = 0.0f; }
    for (int e = gt; e < In * Hn; e += NTOT) {
        int k = e >> 12, h = e & (Hn - 1);
        g_w1t[e] = w1[(size_t)h * In + k];
    }
    for (int e = gt; e < Hn * On; e += NTOT) {
        int k = e >> 10, o = e & (On - 1);
        g_w2t[e] = w2[(size_t)o * Hn + k];
    }
    for (size_t e = gt; e < (size_t)Tn * In * Bn; e += NTOT) {
        size_t t = e >> 16;                 // In*Bn = 65536
        int r = (int)(e & 65535);
        int i = r >> 6, b = r & 63;
        g_xt[e] = x[(t << 16) + (size_t)b * In + i];
    }
    gridbar();

    phaseA(0, gt);
    gridbar();

    for (int t = 0; t < Tn; t++) {
        // P1: GEMM2 chunk partials. item = (chunk: bid>>6, h-tile: bid&63)
        {
            const int chunk = blockIdx.x >> 6;
            const int n0 = (blockIdx.x & 63) * 64;
            gemm_chunk<Hn>(g_w1t, g_spk1, g_p2[chunk], n0, chunk * 512, w_s, s_s);
        }
        gridbar();
        // P2: layer-2 neurons (combine p2); layer-3 (t-1); layer-1 (t+1)
        phaseL2(gt);
        if (t > 0) phaseL3(out, t - 1, gt);
        if (t + 1 < Tn) phaseA(t + 1, gt);
        gridbar();
        // P3: GEMM3 chunk partials. item = (chunk: bid>>4, o-tile: bid&15)
        {
            const int chunk = blockIdx.x >> 4;
            const int n0 = (blockIdx.x & 15) * 64;
            gemm_chunk<On>(g_w2t, g_spk2, g_p3[chunk], n0, chunk * 512, w_s, s_s);
        }
        gridbar();
    }
    phaseL3(out, Tn - 1, gt);
}

extern "C" void kernel_launch(void* const* d_in, const int* in_sizes, int n_in,
                              void* d_out, int out_size) {
    const float* x  = (const float*)d_in[0];   // [512,64,1024]
    const float* w1 = (const float*)d_in[1];   // [4096,1024]
    const float* w2 = (const float*)d_in[2];   // [1024,4096]
    float* out = (float*)d_out;                // [512,64,1024]
    snn_kernel<<<NCTA, NTHR>>>(x, w1, w2, out);
}